// round 5
// baseline (speedup 1.0000x reference)
#include <cuda_runtime.h>

#define BATCH 64
#define FEAT  784
#define DIM   1001
#define DIMSQ (DIM * DIM)        // 1002001 (odd; DIMSQ % 4 == 1, DIM % 4 == 1)
#define ROWS_PER_CTA 56
#define CTAS_X 18                // 18*56 = 1008 >= 1001

// Row-start element offset o = b*DIMSQ + i*DIM  ->  o mod 4 == (b + i) mod 4.
// Aligned quads in row start at j == A (mod 4) with A = (4 - ((b+i)&3)) & 3.
// Thread t's register windows:
//   w0[0..7] = s[4t .. 4t+8)        covers pass-0 quad j = A + 4t   (slice w0[A..A+3])
//   w1[0..7] = s[512+4t .. +8)      covers pass-1 quad j = A + 512 + 4t
__global__ void __launch_bounds__(128, 8) amp_kernel(const float* __restrict__ x,
                                                     float* __restrict__ out) {
    __shared__ float s_sm[1032];      // scaled state, zero-padded past FEAT
    __shared__ float red[4];
    __shared__ float s_inv;

    const int tid = threadIdx.x;
    const int b   = blockIdx.y;
    const float* xb = x + b * FEAT;

    // ---- norm (once per CTA; single wave => once per SM-slot) ----
    float p = 0.0f;
    #pragma unroll
    for (int j = tid; j < FEAT; j += 128) { float v = xb[j]; p += v * v; }
    #pragma unroll
    for (int o = 16; o > 0; o >>= 1) p += __shfl_xor_sync(0xFFFFFFFFu, p, o);
    if ((tid & 31) == 0) red[tid >> 5] = p;
    __syncthreads();
    if (tid == 0) s_inv = rsqrtf(red[0] + red[1] + red[2] + red[3]);
    __syncthreads();
    const float inv = s_inv;

    for (int j = tid; j < 1032; j += 128)
        s_sm[j] = (j < FEAT) ? xb[j] * inv : 0.0f;
    __syncthreads();

    // ---- register windows ----
    float w0[8], w1[8];
    {
        const float4 a0 = *reinterpret_cast<const float4*>(&s_sm[4 * tid]);
        const float4 a1 = *reinterpret_cast<const float4*>(&s_sm[4 * tid + 4]);
        const float4 b0 = *reinterpret_cast<const float4*>(&s_sm[512 + 4 * tid]);
        const float4 b1 = *reinterpret_cast<const float4*>(&s_sm[512 + 4 * tid + 4]);
        w0[0]=a0.x; w0[1]=a0.y; w0[2]=a0.z; w0[3]=a0.w;
        w0[4]=a1.x; w0[5]=a1.y; w0[6]=a1.z; w0[7]=a1.w;
        w1[0]=b0.x; w1[1]=b0.y; w1[2]=b0.z; w1[3]=b0.w;
        w1[4]=b1.x; w1[5]=b1.y; w1[6]=b1.z; w1[7]=b1.w;
    }

    const int i0   = blockIdx.x * ROWS_PER_CTA;
    const int iend = (i0 + ROWS_PER_CTA < DIM) ? (i0 + ROWS_PER_CTA) : DIM;

    // One row with compile-time alignment phase A.
    auto do_row = [&](int i, auto Ac) {
        constexpr int A = decltype(Ac)::value;
        const float si = s_sm[i];
        float* rowp = out + (size_t)b * DIMSQ + (size_t)i * DIM;

        // head scalars j in [0, A)
        if (A > 0 && tid < A) rowp[tid] = si * s_sm[tid];
        // tail scalars: j >= ts are all >= 998 >= FEAT -> zero
        constexpr int TS = (A == 0) ? 1000 : (A == 1) ? 1001 : (A == 2) ? 998 : 999;
        if (DIM - TS > 0 && tid >= 8 && tid < 8 + (DIM - TS)) rowp[TS + tid - 8] = 0.0f;

        float4 v0 = make_float4(si * w0[A], si * w0[A + 1], si * w0[A + 2], si * w0[A + 3]);
        const int j0 = A + 4 * tid;
        __stcs(reinterpret_cast<float4*>(rowp + j0), v0);

        const int j1 = j0 + 512;
        if (j1 <= DIM - 4) {
            float4 v1 = make_float4(si * w1[A], si * w1[A + 1], si * w1[A + 2], si * w1[A + 3]);
            __stcs(reinterpret_cast<float4*>(rowp + j1), v1);
        }
    };

    // Generic (runtime-phase) row for leftovers.
    auto do_row_dyn = [&](int i) {
        const int a = (4 - ((b + i) & 3)) & 3;
        switch (a) {
            case 0: do_row(i, std::integral_constant<int, 0>{}); break;
            case 1: do_row(i, std::integral_constant<int, 1>{}); break;
            case 2: do_row(i, std::integral_constant<int, 2>{}); break;
            default: do_row(i, std::integral_constant<int, 3>{}); break;
        }
    };

    // Phase of the first row group is fixed per CTA: specialize once.
    const int m0 = (b + i0) & 3;
    const int ng = (iend - i0) >> 2;      // full groups of 4
    const int ig_end = i0 + 4 * ng;

    // For group row k: (b+i)&3 = (m0+k)&3, A_k = (4-(m0+k))&3 — static per case.
    #define GROUP_BODY(M)                                                            \
        for (int ig = i0; ig < ig_end; ig += 4) {                                    \
            do_row(ig + 0, std::integral_constant<int, (4 - ((M) + 0)) & 3>{});      \
            do_row(ig + 1, std::integral_constant<int, (4 - ((M) + 1)) & 3>{});      \
            do_row(ig + 2, std::integral_constant<int, (4 - ((M) + 2)) & 3>{});      \
            do_row(ig + 3, std::integral_constant<int, (4 - ((M) + 3)) & 3>{});      \
        }
    switch (m0) {
        case 0: GROUP_BODY(0); break;
        case 1: GROUP_BODY(1); break;
        case 2: GROUP_BODY(2); break;
        default: GROUP_BODY(3); break;
    }
    #undef GROUP_BODY

    for (int i = ig_end; i < iend; ++i) do_row_dyn(i);
}

extern "C" void kernel_launch(void* const* d_in, const int* in_sizes, int n_in,
                              void* d_out, int out_size) {
    const float* x   = (const float*)d_in[0];
    float*       out = (float*)d_out;
    amp_kernel<<<dim3(CTAS_X, BATCH), 128>>>(x, out);
}